// round 4
// baseline (speedup 1.0000x reference)
#include <cuda_runtime.h>
#include <cuda_bf16.h>

// PersistenceLandscapeLayer — split-P two-kernel version.
// K1: (S x B) CTAs, each gathers CHUNK pairs, filters (death>birth && dim==d),
//     compacts to smem, computes per-chunk top-4 per (d,t) cell -> global partials.
// K2: merges S partial top-4s per cell -> final [B, D, T, KMAX].

constexpr int TT     = 32;
constexpr int D_HOM  = 2;
constexpr int KMAX   = 4;
constexpr int NCELL  = D_HOM * TT;          // 64 cells per batch row
constexpr int CHUNK  = 512;                 // pairs per CTA (== NTH1: 1 pair/thread)
constexpr int NTH1   = 512;
constexpr int MAXB   = 128;
constexpr int MAXS   = 16;                  // supports P up to 8192
constexpr unsigned FULL = 0xffffffffu;

// Scratch: per-(batch, split) partial top-4 for every cell. 128*16*64*16B = 2MB.
__device__ float4 g_part[MAXB * MAXS * NCELL];

__global__ __launch_bounds__(NTH1, 4)
void pl_part(const float* __restrict__ fun,
             const int*   __restrict__ bidx,
             const int*   __restrict__ didx,
             const int*   __restrict__ pdim,
             int N, int P, int S)
{
    __shared__ float2 lst[D_HOM][CHUNK];    // exact-capacity: cannot overflow
    __shared__ int    cnt[D_HOM];

    const int tid  = threadIdx.x;
    const int lane = tid & 31;
    const int ss   = blockIdx.x;            // split
    const int bb   = blockIdx.y;            // batch row

    const float* frow = fun  + (size_t)bb * N;
    const int*   brow = bidx + (size_t)bb * P;
    const int*   drow = didx + (size_t)bb * P;
    const int*   prow = pdim + (size_t)bb * P;

    if (tid < D_HOM) cnt[tid] = 0;
    __syncthreads();

    // ---- Phase 1: one pair per thread, full-MLP gather + filter + compact ----
    const int p   = ss * CHUNK + tid;
    bool  act = (p < P);
    float bv = 0.0f, dv = 0.0f;
    int   dm = 0;
    if (act) {
        int bi = brow[p];
        int di = drow[p];
        dm = prow[p];
        bv = __ldg(frow + bi);
        dv = __ldg(frow + di);
    }
    bool keep = act && (dv > bv);           // tent <= 0 otherwise -> clamps to 0
    #pragma unroll
    for (int dd = 0; dd < D_HOM; ++dd) {
        unsigned m = __ballot_sync(FULL, keep && (dm == dd));
        if (m) {                            // warp-uniform
            int leader = __ffs(m) - 1;
            int cbase  = 0;
            if (lane == leader) cbase = atomicAdd(&cnt[dd], __popc(m));
            cbase = __shfl_sync(FULL, cbase, leader);
            if (keep && dm == dd) {
                int off = cbase + __popc(m & ((1u << lane) - 1u));
                lst[dd][off] = make_float2(bv, dv);
            }
        }
    }
    __syncthreads();

    // ---- Phase 2: 16 warps; warp w -> dim (w>>3), t-cells [(w&7)*4 .. +4) ----
    const int w     = tid >> 5;
    const int dd    = w >> 3;
    const int tbase = (w & 7) * 4;
    const int n     = cnt[dd];
    const float2* L = lst[dd];

    float tv[4];
    #pragma unroll
    for (int j = 0; j < 4; ++j) tv[j] = (float)(tbase + j + 1) * (1.0f / (float)TT);

    float top[4][4];
    #pragma unroll
    for (int j = 0; j < 4; ++j)
        #pragma unroll
        for (int k = 0; k < 4; ++k) top[j][k] = 0.0f;

    for (int i = lane; i < n; i += 32) {
        float2 bd = L[i];
        #pragma unroll
        for (int j = 0; j < 4; ++j) {
            // identical op order to reference: max(min(t-b, d-t), 0)
            float m = fmaxf(fminf(tv[j] - bd.x, bd.y - tv[j]), 0.0f);
            float mx;
            mx = fmaxf(top[j][0], m); m = fminf(top[j][0], m); top[j][0] = mx;
            mx = fmaxf(top[j][1], m); m = fminf(top[j][1], m); top[j][1] = mx;
            mx = fmaxf(top[j][2], m); m = fminf(top[j][2], m); top[j][2] = mx;
            top[j][3] = fmaxf(top[j][3], m);
        }
    }

    // ---- Phase 3: butterfly merge of per-lane sorted-4 lists (descending) ----
    #pragma unroll
    for (int off = 16; off; off >>= 1) {
        #pragma unroll
        for (int j = 0; j < 4; ++j) {
            float r0 = __shfl_xor_sync(FULL, top[j][0], off);
            float r1 = __shfl_xor_sync(FULL, top[j][1], off);
            float r2 = __shfl_xor_sync(FULL, top[j][2], off);
            float r3 = __shfl_xor_sync(FULL, top[j][3], off);
            // max-half of bitonic [a0..a3, r3..r0], then bitonic-sort-4 desc
            float l0 = fmaxf(top[j][0], r3);
            float l1 = fmaxf(top[j][1], r2);
            float l2 = fmaxf(top[j][2], r1);
            float l3 = fmaxf(top[j][3], r0);
            float x0 = fmaxf(l0, l2), x2 = fminf(l0, l2);
            float x1 = fmaxf(l1, l3), x3 = fminf(l1, l3);
            top[j][0] = fmaxf(x0, x1); top[j][1] = fminf(x0, x1);
            top[j][2] = fmaxf(x2, x3); top[j][3] = fminf(x2, x3);
        }
    }

    if (lane == 0) {
        float4* dst = &g_part[((size_t)bb * S + ss) * NCELL + dd * TT + tbase];
        #pragma unroll
        for (int j = 0; j < 4; ++j)
            dst[j] = make_float4(top[j][0], top[j][1], top[j][2], top[j][3]);
    }
}

__global__ __launch_bounds__(256)
void pl_merge(float* __restrict__ out, int B, int S)
{
    int idx = blockIdx.x * blockDim.x + threadIdx.x;   // one thread per cell
    if (idx >= B * NCELL) return;
    int bb = idx / NCELL;
    int c  = idx - bb * NCELL;

    float a0 = 0.f, a1 = 0.f, a2 = 0.f, a3 = 0.f;
    const float4* src = &g_part[(size_t)bb * S * NCELL + c];
    for (int s = 0; s < S; ++s) {
        float4 v = src[(size_t)s * NCELL];
        float m, mx;
        #pragma unroll
        for (int k = 0; k < 4; ++k) {
            m = (k == 0) ? v.x : (k == 1) ? v.y : (k == 2) ? v.z : v.w;
            mx = fmaxf(a0, m); m = fminf(a0, m); a0 = mx;
            mx = fmaxf(a1, m); m = fminf(a1, m); a1 = mx;
            mx = fmaxf(a2, m); m = fminf(a2, m); a2 = mx;
            a3 = fmaxf(a3, m);
        }
    }
    ((float4*)out)[idx] = make_float4(a0, a1, a2, a3);
}

extern "C" void kernel_launch(void* const* d_in, const int* in_sizes, int n_in,
                              void* d_out, int out_size)
{
    const float* fun = (const float*)d_in[0];
    const int*   bi  = (const int*)  d_in[1];
    const int*   di  = (const int*)  d_in[2];
    const int*   pd  = (const int*)  d_in[3];
    float*       out = (float*)d_out;

    int B = out_size / (D_HOM * TT * KMAX);
    int N = in_sizes[0] / B;
    int P = in_sizes[1] / B;
    int S = (P + CHUNK - 1) / CHUNK;        // 8 for P=4096
    if (S > MAXS) S = MAXS;                 // scratch bound (never hit for P<=8192)

    dim3 g1(S, B);
    pl_part<<<g1, NTH1>>>(fun, bi, di, pd, N, P, S);

    int cells = B * NCELL;
    pl_merge<<<(cells + 255) / 256, 256>>>(out, B, S);
}

// round 5
// speedup vs baseline: 1.5118x; 1.5118x over previous
#include <cuda_runtime.h>
#include <cuda_bf16.h>

// PersistenceLandscapeLayer — single fused kernel, split-P with last-CTA merge.
// Grid (S x B): each CTA gathers CHUNK pairs, filters (death>birth && dim==d),
// compacts to smem, computes per-chunk top-4 per (d,t) cell -> global partials.
// The last CTA of each batch row (threadfence-reduction pattern) merges the S
// partials and writes the final [B, D, T, KMAX] output.

constexpr int TT     = 32;
constexpr int D_HOM  = 2;
constexpr int KMAX   = 4;
constexpr int NCELL  = D_HOM * TT;          // 64 cells per batch row
constexpr int CHUNK  = 512;                 // pairs per CTA (== NTH: 1 pair/thread)
constexpr int NTH    = 512;
constexpr int MAXB   = 128;
constexpr int MAXS   = 16;                  // supports P up to 8192
constexpr unsigned FULL = 0xffffffffu;

// Scratch: per-(batch, split) partial top-4 for every cell. 128*16*64*16B = 2MB.
__device__ float4 g_part[MAXB * MAXS * NCELL];
__device__ int    g_cnt[MAXB];              // zero-init; reset to 0 by last CTA

__global__ __launch_bounds__(NTH)
void pl_fused(const float* __restrict__ fun,
              const int*   __restrict__ bidx,
              const int*   __restrict__ didx,
              const int*   __restrict__ pdim,
              float*       __restrict__ out,
              int N, int P, int S)
{
    __shared__ float2 lst[D_HOM][CHUNK];    // exact-capacity: cannot overflow
    __shared__ int    cnt[D_HOM];
    __shared__ int    isLast;

    const int tid  = threadIdx.x;
    const int lane = tid & 31;
    const int ss   = blockIdx.x;            // split
    const int bb   = blockIdx.y;            // batch row

    const float* frow = fun  + (size_t)bb * N;
    const int*   brow = bidx + (size_t)bb * P;
    const int*   drow = didx + (size_t)bb * P;
    const int*   prow = pdim + (size_t)bb * P;

    if (tid < D_HOM) cnt[tid] = 0;
    __syncthreads();

    // ---- Phase 1: one pair per thread, full-MLP gather + filter + compact ----
    {
        const int p   = ss * CHUNK + tid;
        bool  act = (p < P);
        float bv = 0.0f, dv = 0.0f;
        int   dm = 0;
        if (act) {
            int bi = brow[p];
            int di = drow[p];
            dm = prow[p];
            bv = __ldg(frow + bi);
            dv = __ldg(frow + di);
        }
        bool keep = act && (dv > bv);       // tent <= 0 otherwise -> clamps to 0
        #pragma unroll
        for (int dd = 0; dd < D_HOM; ++dd) {
            unsigned m = __ballot_sync(FULL, keep && (dm == dd));
            if (m) {                        // warp-uniform
                int leader = __ffs(m) - 1;
                int cbase  = 0;
                if (lane == leader) cbase = atomicAdd(&cnt[dd], __popc(m));
                cbase = __shfl_sync(FULL, cbase, leader);
                if (keep && dm == dd) {
                    int off = cbase + __popc(m & ((1u << lane) - 1u));
                    lst[dd][off] = make_float2(bv, dv);
                }
            }
        }
    }
    __syncthreads();

    // ---- Phase 2: one (d,t) cell per 8-lane subgroup (64 cells total) ----
    // warp w (0..15) covers cells [4w, 4w+4); cells 0..31 = dim0, 32..63 = dim1.
    const int   w    = tid >> 5;
    const int   cell = (w << 2) + (lane >> 3);
    const int   dd   = cell >> 5;
    const int   t    = cell & (TT - 1);
    const int   sub  = lane & 7;
    const float tv   = (float)(t + 1) * (1.0f / (float)TT);
    const int   n    = cnt[dd];
    const float2* L  = lst[dd];

    float t0 = 0.f, t1 = 0.f, t2 = 0.f, t3 = 0.f;   // sorted desc top-4
    for (int i = sub; i < n; i += 8) {
        float2 bd = L[i];                    // broadcast within warp (same addr)
        // identical op order to reference: max(min(t-b, d-t), 0)
        float m = fmaxf(fminf(tv - bd.x, bd.y - tv), 0.0f);
        float mx;
        mx = fmaxf(t0, m); m = fminf(t0, m); t0 = mx;
        mx = fmaxf(t1, m); m = fminf(t1, m); t1 = mx;
        mx = fmaxf(t2, m); m = fminf(t2, m); t2 = mx;
        t3 = fmaxf(t3, m);
    }

    // 3-stage butterfly merge within the 8-lane subgroup (xor stays in-group)
    #pragma unroll
    for (int off = 4; off; off >>= 1) {
        float r0 = __shfl_xor_sync(FULL, t0, off);
        float r1 = __shfl_xor_sync(FULL, t1, off);
        float r2 = __shfl_xor_sync(FULL, t2, off);
        float r3 = __shfl_xor_sync(FULL, t3, off);
        // max-half of bitonic [t0..t3, r3..r0], then bitonic-sort-4 desc
        float l0 = fmaxf(t0, r3), l1 = fmaxf(t1, r2);
        float l2 = fmaxf(t2, r1), l3 = fmaxf(t3, r0);
        float x0 = fmaxf(l0, l2), x2 = fminf(l0, l2);
        float x1 = fmaxf(l1, l3), x3 = fminf(l1, l3);
        t0 = fmaxf(x0, x1); t1 = fminf(x0, x1);
        t2 = fmaxf(x2, x3); t3 = fminf(x2, x3);
    }

    if (sub == 0) {
        g_part[((size_t)bb * S + ss) * NCELL + cell] = make_float4(t0, t1, t2, t3);
        __threadfence();                    // writer's partials visible device-wide
    }
    __syncthreads();                        // fences happen-before tid0's atomic

    // ---- Phase 3: last CTA of this batch row merges all S partials ----
    if (tid == 0) {
        int v = atomicAdd(&g_cnt[bb], 1);
        isLast = (v == S - 1);
        if (isLast) g_cnt[bb] = 0;          // reset for next graph replay
    }
    __syncthreads();

    if (isLast) {
        if (tid == 0) __threadfence();      // acquire-side fence
        __syncthreads();
        if (tid < NCELL) {
            const float4* src = &g_part[(size_t)bb * S * NCELL + tid];
            float a0 = 0.f, a1 = 0.f, a2 = 0.f, a3 = 0.f;
            for (int s = 0; s < S; ++s) {
                float4 v = __ldcg(src + (size_t)s * NCELL);  // bypass stale L1
                float m, mx;
                #pragma unroll
                for (int k = 0; k < 4; ++k) {
                    m = (k == 0) ? v.x : (k == 1) ? v.y : (k == 2) ? v.z : v.w;
                    mx = fmaxf(a0, m); m = fminf(a0, m); a0 = mx;
                    mx = fmaxf(a1, m); m = fminf(a1, m); a1 = mx;
                    mx = fmaxf(a2, m); m = fminf(a2, m); a2 = mx;
                    a3 = fmaxf(a3, m);
                }
            }
            ((float4*)out)[(size_t)bb * NCELL + tid] = make_float4(a0, a1, a2, a3);
        }
    }
}

extern "C" void kernel_launch(void* const* d_in, const int* in_sizes, int n_in,
                              void* d_out, int out_size)
{
    const float* fun = (const float*)d_in[0];
    const int*   bi  = (const int*)  d_in[1];
    const int*   di  = (const int*)  d_in[2];
    const int*   pd  = (const int*)  d_in[3];
    float*       out = (float*)d_out;

    int B = out_size / (D_HOM * TT * KMAX);
    int N = in_sizes[0] / B;
    int P = in_sizes[1] / B;
    int S = (P + CHUNK - 1) / CHUNK;        // 8 for P=4096
    if (S > MAXS) S = MAXS;                 // scratch bound (never hit for P<=8192)

    dim3 g(S, B);
    pl_fused<<<g, NTH>>>(fun, bi, di, pd, out, N, P, S);
}